// round 3
// baseline (speedup 1.0000x reference)
#include <cuda_runtime.h>
#include <cuda_bf16.h>
#include <math.h>

// Problem constants
#define B_WIN   4096
#define NTOK    49
#define CDIM    512
#define NHEAD   16
#define HDIM    32
#define NW      64
#define THREEC  1536
#define MROWS   (B_WIN * NTOK)          // 200704
#define SCALE   0.17677669529663687f    // 32^-0.5

// Scratch (allocation-free: __device__ globals)
__device__ float g_qkv[(size_t)MROWS * THREEC];   // [M, 3C]
__device__ float g_att[(size_t)MROWS * CDIM];     // [M, C]

// ---------------------------------------------------------------------------
// SGEMM with bias: Out[M,N] = A[M,K] @ W[K,N] + bias[N]
// BM=BN=128, BK=8, 256 threads, 8x8 per thread, double-buffered smem.
// Requires M%128==0, N%128==0, K%8==0 (true for all uses here).
// ---------------------------------------------------------------------------
__global__ __launch_bounds__(256, 2)
void sgemm_bias_kernel(const float* __restrict__ A,
                       const float* __restrict__ W,
                       const float* __restrict__ bias,
                       float* __restrict__ Out,
                       int M, int N, int K)
{
    const int BM = 128, BN = 128, BK = 8;
    __shared__ __align__(16) float As[2][BK][BM];
    __shared__ __align__(16) float Bs[2][BK][BN];

    const int tid = threadIdx.x;
    const int block_m = blockIdx.y * BM;
    const int block_n = blockIdx.x * BN;

    // A tile load mapping: 128x8 floats = 256 float4, one per thread
    const int a_row = tid >> 1;           // 0..127
    const int a_col = (tid & 1) << 2;     // 0 or 4
    // B tile load mapping: 8x128 floats = 256 float4, one per thread
    const int b_row = tid >> 5;           // 0..7
    const int b_col = (tid & 31) << 2;    // 0..124

    const int tx = tid & 15;              // 0..15 -> n
    const int ty = tid >> 4;              // 0..15 -> m

    float acc[8][8];
#pragma unroll
    for (int i = 0; i < 8; ++i)
#pragma unroll
        for (int j = 0; j < 8; ++j) acc[i][j] = 0.0f;

    const int nk = K / BK;

    // Preload tile 0
    float4 ra = *reinterpret_cast<const float4*>(&A[(size_t)(block_m + a_row) * K + a_col]);
    float4 rb = *reinterpret_cast<const float4*>(&W[(size_t)b_row * N + block_n + b_col]);
    As[0][a_col + 0][a_row] = ra.x;
    As[0][a_col + 1][a_row] = ra.y;
    As[0][a_col + 2][a_row] = ra.z;
    As[0][a_col + 3][a_row] = ra.w;
    *reinterpret_cast<float4*>(&Bs[0][b_row][b_col]) = rb;
    __syncthreads();

    for (int kt = 0; kt < nk; ++kt) {
        const int cur = kt & 1;
        if (kt + 1 < nk) {
            const int k0 = (kt + 1) * BK;
            ra = *reinterpret_cast<const float4*>(&A[(size_t)(block_m + a_row) * K + k0 + a_col]);
            rb = *reinterpret_cast<const float4*>(&W[(size_t)(k0 + b_row) * N + block_n + b_col]);
        }
#pragma unroll
        for (int kk = 0; kk < BK; ++kk) {
            float af[8], bf[8];
            *reinterpret_cast<float4*>(&af[0]) = *reinterpret_cast<const float4*>(&As[cur][kk][ty * 8]);
            *reinterpret_cast<float4*>(&af[4]) = *reinterpret_cast<const float4*>(&As[cur][kk][ty * 8 + 4]);
            *reinterpret_cast<float4*>(&bf[0]) = *reinterpret_cast<const float4*>(&Bs[cur][kk][tx * 8]);
            *reinterpret_cast<float4*>(&bf[4]) = *reinterpret_cast<const float4*>(&Bs[cur][kk][tx * 8 + 4]);
#pragma unroll
            for (int i = 0; i < 8; ++i)
#pragma unroll
                for (int j = 0; j < 8; ++j)
                    acc[i][j] = fmaf(af[i], bf[j], acc[i][j]);
        }
        if (kt + 1 < nk) {
            const int nxt = cur ^ 1;
            As[nxt][a_col + 0][a_row] = ra.x;
            As[nxt][a_col + 1][a_row] = ra.y;
            As[nxt][a_col + 2][a_row] = ra.z;
            As[nxt][a_col + 3][a_row] = ra.w;
            *reinterpret_cast<float4*>(&Bs[nxt][b_row][b_col]) = rb;
            __syncthreads();
        }
    }

    // Epilogue: add bias, store
    float bv[8];
#pragma unroll
    for (int j = 0; j < 8; ++j) bv[j] = bias[block_n + tx * 8 + j];

#pragma unroll
    for (int i = 0; i < 8; ++i) {
        const size_t row = (size_t)(block_m + ty * 8 + i);
        float* op = &Out[row * N + block_n + tx * 8];
        float4 o0, o1;
        o0.x = acc[i][0] + bv[0]; o0.y = acc[i][1] + bv[1];
        o0.z = acc[i][2] + bv[2]; o0.w = acc[i][3] + bv[3];
        o1.x = acc[i][4] + bv[4]; o1.y = acc[i][5] + bv[5];
        o1.z = acc[i][6] + bv[6]; o1.w = acc[i][7] + bv[7];
        *reinterpret_cast<float4*>(op)     = o0;
        *reinterpret_cast<float4*>(op + 4) = o1;
    }
}

// ---------------------------------------------------------------------------
// Attention kernel: one block per (window b, head h).
// Loads q,k,v from g_qkv, computes softmax((q*scale)k^T + bias + mask) v,
// writes to g_att with heads re-interleaved into [b, n, h*hd + d].
// ---------------------------------------------------------------------------
__global__ __launch_bounds__(256)
void attn_kernel(const float* __restrict__ mask,
                 const float* __restrict__ bias_table,   // [169, 16]
                 const int*   __restrict__ rel_idx)      // [49*49]
{
    const int b = blockIdx.x >> 4;
    const int h = blockIdx.x & 15;
    const int tid = threadIdx.x;

    __shared__ float q[NTOK][HDIM + 1];
    __shared__ float k[NTOK][HDIM + 1];
    __shared__ float v[NTOK][HDIM + 1];
    __shared__ float s[NTOK][NTOK + 1];

    // Load q,k,v for this (b,h). Coalesced over d.
    for (int idx = tid; idx < NTOK * HDIM; idx += 256) {
        const int n = idx >> 5;
        const int d = idx & 31;
        const size_t base = ((size_t)(b * NTOK + n)) * THREEC + h * HDIM + d;
        q[n][d] = g_qkv[base] * SCALE;
        k[n][d] = g_qkv[base + CDIM];
        v[n][d] = g_qkv[base + 2 * CDIM];
    }
    __syncthreads();

    // Scores + bias + mask
    const float* mrow = &mask[(size_t)(b & 63) * (NTOK * NTOK)];
    for (int p = tid; p < NTOK * NTOK; p += 256) {
        const int i = p / NTOK;
        const int j = p - i * NTOK;
        float acc = 0.0f;
#pragma unroll
        for (int d = 0; d < HDIM; ++d)
            acc = fmaf(q[i][d], k[j][d], acc);
        acc += bias_table[rel_idx[p] * NHEAD + h] + mrow[p];
        s[i][j] = acc;
    }
    __syncthreads();

    // Row softmax (49 rows, one thread each)
    if (tid < NTOK) {
        float m = -1e30f;
#pragma unroll
        for (int c = 0; c < NTOK; ++c) m = fmaxf(m, s[tid][c]);
        float sum = 0.0f;
#pragma unroll
        for (int c = 0; c < NTOK; ++c) {
            const float e = __expf(s[tid][c] - m);
            s[tid][c] = e;
            sum += e;
        }
        const float inv = 1.0f / sum;
#pragma unroll
        for (int c = 0; c < NTOK; ++c) s[tid][c] *= inv;
    }
    __syncthreads();

    // out = s @ v ; write with head interleave
    for (int p = tid; p < NTOK * HDIM; p += 256) {
        const int i = p >> 5;
        const int d = p & 31;
        float acc = 0.0f;
#pragma unroll
        for (int j = 0; j < NTOK; ++j)
            acc = fmaf(s[i][j], v[j][d], acc);
        g_att[((size_t)(b * NTOK + i)) * CDIM + h * HDIM + d] = acc;
    }
}

// ---------------------------------------------------------------------------
// Launch
// ---------------------------------------------------------------------------
extern "C" void kernel_launch(void* const* d_in, const int* in_sizes, int n_in,
                              void* d_out, int out_size)
{
    const float* x          = (const float*)d_in[0];
    const float* mask       = (const float*)d_in[1];
    const float* qkv_w      = (const float*)d_in[2];
    const float* qkv_b      = (const float*)d_in[3];
    const float* proj_w     = (const float*)d_in[4];
    const float* proj_b     = (const float*)d_in[5];
    const float* bias_table = (const float*)d_in[6];
    const int*   rel_idx    = (const int*)d_in[7];
    float* out = (float*)d_out;

    void* qkv_ptr = nullptr;
    void* att_ptr = nullptr;
    cudaGetSymbolAddress(&qkv_ptr, g_qkv);
    cudaGetSymbolAddress(&att_ptr, g_att);
    float* qkv = (float*)qkv_ptr;
    float* att = (float*)att_ptr;

    // 1) QKV GEMM: [200704,512] @ [512,1536] + b
    dim3 g1(THREEC / 128, MROWS / 128);
    sgemm_bias_kernel<<<g1, 256>>>(x, qkv_w, qkv_b, qkv, MROWS, THREEC, CDIM);

    // 2) Windowed attention per (b, h)
    attn_kernel<<<B_WIN * NHEAD, 256>>>(mask, bias_table, rel_idx);

    // 3) Proj GEMM: [200704,512] @ [512,512] + b
    dim3 g2(CDIM / 128, MROWS / 128);
    sgemm_bias_kernel<<<g2, 256>>>(att, proj_w, proj_b, out, MROWS, CDIM, CDIM);
}

// round 4
// speedup vs baseline: 1.0005x; 1.0005x over previous
#include <cuda_runtime.h>
#include <cuda_bf16.h>
#include <math.h>

// Problem constants
#define B_WIN   4096
#define NTOK    49
#define CDIM    512
#define NHEAD   16
#define HDIM    32
#define NW      64
#define THREEC  1536
#define MROWS   (B_WIN * NTOK)          // 200704
#define SCALE   0.17677669529663687f    // 32^-0.5

// Scratch (allocation-free: __device__ globals)
__device__ float g_qkv[(size_t)MROWS * THREEC];   // [M, 3C]
__device__ float g_att[(size_t)MROWS * CDIM];     // [M, C]

// ---------------------------------------------------------------------------
// SGEMM with bias: Out[M,N] = A[M,K] @ W[K,N] + bias[N]
// BM=BN=128, BK=8, 256 threads, 8x8 per thread, double-buffered smem.
// Requires M%128==0, N%128==0, K%8==0 (true for all uses here).
// ---------------------------------------------------------------------------
__global__ __launch_bounds__(256, 2)
void sgemm_bias_kernel(const float* __restrict__ A,
                       const float* __restrict__ W,
                       const float* __restrict__ bias,
                       float* __restrict__ Out,
                       int M, int N, int K)
{
    const int BM = 128, BN = 128, BK = 8;
    __shared__ __align__(16) float As[2][BK][BM];
    __shared__ __align__(16) float Bs[2][BK][BN];

    const int tid = threadIdx.x;
    const int block_m = blockIdx.y * BM;
    const int block_n = blockIdx.x * BN;

    // A tile load mapping: 128x8 floats = 256 float4, one per thread
    const int a_row = tid >> 1;           // 0..127
    const int a_col = (tid & 1) << 2;     // 0 or 4
    // B tile load mapping: 8x128 floats = 256 float4, one per thread
    const int b_row = tid >> 5;           // 0..7
    const int b_col = (tid & 31) << 2;    // 0..124

    const int tx = tid & 15;              // 0..15 -> n
    const int ty = tid >> 4;              // 0..15 -> m

    float acc[8][8];
#pragma unroll
    for (int i = 0; i < 8; ++i)
#pragma unroll
        for (int j = 0; j < 8; ++j) acc[i][j] = 0.0f;

    const int nk = K / BK;

    // Preload tile 0
    float4 ra = *reinterpret_cast<const float4*>(&A[(size_t)(block_m + a_row) * K + a_col]);
    float4 rb = *reinterpret_cast<const float4*>(&W[(size_t)b_row * N + block_n + b_col]);
    As[0][a_col + 0][a_row] = ra.x;
    As[0][a_col + 1][a_row] = ra.y;
    As[0][a_col + 2][a_row] = ra.z;
    As[0][a_col + 3][a_row] = ra.w;
    *reinterpret_cast<float4*>(&Bs[0][b_row][b_col]) = rb;
    __syncthreads();

    for (int kt = 0; kt < nk; ++kt) {
        const int cur = kt & 1;
        if (kt + 1 < nk) {
            const int k0 = (kt + 1) * BK;
            ra = *reinterpret_cast<const float4*>(&A[(size_t)(block_m + a_row) * K + k0 + a_col]);
            rb = *reinterpret_cast<const float4*>(&W[(size_t)(k0 + b_row) * N + block_n + b_col]);
        }
#pragma unroll
        for (int kk = 0; kk < BK; ++kk) {
            float af[8], bf[8];
            *reinterpret_cast<float4*>(&af[0]) = *reinterpret_cast<const float4*>(&As[cur][kk][ty * 8]);
            *reinterpret_cast<float4*>(&af[4]) = *reinterpret_cast<const float4*>(&As[cur][kk][ty * 8 + 4]);
            *reinterpret_cast<float4*>(&bf[0]) = *reinterpret_cast<const float4*>(&Bs[cur][kk][tx * 8]);
            *reinterpret_cast<float4*>(&bf[4]) = *reinterpret_cast<const float4*>(&Bs[cur][kk][tx * 8 + 4]);
#pragma unroll
            for (int i = 0; i < 8; ++i)
#pragma unroll
                for (int j = 0; j < 8; ++j)
                    acc[i][j] = fmaf(af[i], bf[j], acc[i][j]);
        }
        if (kt + 1 < nk) {
            const int nxt = cur ^ 1;
            As[nxt][a_col + 0][a_row] = ra.x;
            As[nxt][a_col + 1][a_row] = ra.y;
            As[nxt][a_col + 2][a_row] = ra.z;
            As[nxt][a_col + 3][a_row] = ra.w;
            *reinterpret_cast<float4*>(&Bs[nxt][b_row][b_col]) = rb;
            __syncthreads();
        }
    }

    // Epilogue: add bias, store
    float bv[8];
#pragma unroll
    for (int j = 0; j < 8; ++j) bv[j] = bias[block_n + tx * 8 + j];

#pragma unroll
    for (int i = 0; i < 8; ++i) {
        const size_t row = (size_t)(block_m + ty * 8 + i);
        float* op = &Out[row * N + block_n + tx * 8];
        float4 o0, o1;
        o0.x = acc[i][0] + bv[0]; o0.y = acc[i][1] + bv[1];
        o0.z = acc[i][2] + bv[2]; o0.w = acc[i][3] + bv[3];
        o1.x = acc[i][4] + bv[4]; o1.y = acc[i][5] + bv[5];
        o1.z = acc[i][6] + bv[6]; o1.w = acc[i][7] + bv[7];
        *reinterpret_cast<float4*>(op)     = o0;
        *reinterpret_cast<float4*>(op + 4) = o1;
    }
}

// ---------------------------------------------------------------------------
// Attention kernel: one block per (window b, head h).
// Loads q,k,v from g_qkv, computes softmax((q*scale)k^T + bias + mask) v,
// writes to g_att with heads re-interleaved into [b, n, h*hd + d].
// ---------------------------------------------------------------------------
__global__ __launch_bounds__(256)
void attn_kernel(const float* __restrict__ mask,
                 const float* __restrict__ bias_table,   // [169, 16]
                 const int*   __restrict__ rel_idx)      // [49*49]
{
    const int b = blockIdx.x >> 4;
    const int h = blockIdx.x & 15;
    const int tid = threadIdx.x;

    __shared__ float q[NTOK][HDIM + 1];
    __shared__ float k[NTOK][HDIM + 1];
    __shared__ float v[NTOK][HDIM + 1];
    __shared__ float s[NTOK][NTOK + 1];

    // Load q,k,v for this (b,h). Coalesced over d.
    for (int idx = tid; idx < NTOK * HDIM; idx += 256) {
        const int n = idx >> 5;
        const int d = idx & 31;
        const size_t base = ((size_t)(b * NTOK + n)) * THREEC + h * HDIM + d;
        q[n][d] = g_qkv[base] * SCALE;
        k[n][d] = g_qkv[base + CDIM];
        v[n][d] = g_qkv[base + 2 * CDIM];
    }
    __syncthreads();

    // Scores + bias + mask
    const float* mrow = &mask[(size_t)(b & 63) * (NTOK * NTOK)];
    for (int p = tid; p < NTOK * NTOK; p += 256) {
        const int i = p / NTOK;
        const int j = p - i * NTOK;
        float acc = 0.0f;
#pragma unroll
        for (int d = 0; d < HDIM; ++d)
            acc = fmaf(q[i][d], k[j][d], acc);
        acc += bias_table[rel_idx[p] * NHEAD + h] + mrow[p];
        s[i][j] = acc;
    }
    __syncthreads();

    // Row softmax (49 rows, one thread each)
    if (tid < NTOK) {
        float m = -1e30f;
#pragma unroll
        for (int c = 0; c < NTOK; ++c) m = fmaxf(m, s[tid][c]);
        float sum = 0.0f;
#pragma unroll
        for (int c = 0; c < NTOK; ++c) {
            const float e = __expf(s[tid][c] - m);
            s[tid][c] = e;
            sum += e;
        }
        const float inv = 1.0f / sum;
#pragma unroll
        for (int c = 0; c < NTOK; ++c) s[tid][c] *= inv;
    }
    __syncthreads();

    // out = s @ v ; write with head interleave
    for (int p = tid; p < NTOK * HDIM; p += 256) {
        const int i = p >> 5;
        const int d = p & 31;
        float acc = 0.0f;
#pragma unroll
        for (int j = 0; j < NTOK; ++j)
            acc = fmaf(s[i][j], v[j][d], acc);
        g_att[((size_t)(b * NTOK + i)) * CDIM + h * HDIM + d] = acc;
    }
}

// ---------------------------------------------------------------------------
// Launch
// ---------------------------------------------------------------------------
extern "C" void kernel_launch(void* const* d_in, const int* in_sizes, int n_in,
                              void* d_out, int out_size)
{
    const float* x          = (const float*)d_in[0];
    const float* mask       = (const float*)d_in[1];
    const float* qkv_w      = (const float*)d_in[2];
    const float* qkv_b      = (const float*)d_in[3];
    const float* proj_w     = (const float*)d_in[4];
    const float* proj_b     = (const float*)d_in[5];
    const float* bias_table = (const float*)d_in[6];
    const int*   rel_idx    = (const int*)d_in[7];
    float* out = (float*)d_out;

    void* qkv_ptr = nullptr;
    void* att_ptr = nullptr;
    cudaGetSymbolAddress(&qkv_ptr, g_qkv);
    cudaGetSymbolAddress(&att_ptr, g_att);
    float* qkv = (float*)qkv_ptr;
    float* att = (float*)att_ptr;

    // 1) QKV GEMM: [200704,512] @ [512,1536] + b
    dim3 g1(THREEC / 128, MROWS / 128);
    sgemm_bias_kernel<<<g1, 256>>>(x, qkv_w, qkv_b, qkv, MROWS, THREEC, CDIM);

    // 2) Windowed attention per (b, h)
    attn_kernel<<<B_WIN * NHEAD, 256>>>(mask, bias_table, rel_idx);

    // 3) Proj GEMM: [200704,512] @ [512,512] + b
    dim3 g2(CDIM / 128, MROWS / 128);
    sgemm_bias_kernel<<<g2, 256>>>(att, proj_w, proj_b, out, MROWS, CDIM, CDIM);
}